// round 8
// baseline (speedup 1.0000x reference)
#include <cuda_runtime.h>

#define MAXQ   4096
#define MAXM   100000
#define TILE   512
#define MARGIN 0.0625f

// Scratch (static __device__ — no runtime allocation)
__device__ float4      g_q[MAXQ];            // x, y, z, |q|^2
__device__ unsigned    g_dmin[MAXQ];         // monotonic-mapped min of (|m|^2 - 2 q.m)
__device__ ulonglong2  g_means2[2 * MAXM];   // per mean: {(-2x,-2x),(-2y,-2y)} , {(-2z,-2z),(m2,m2)}

__device__ __forceinline__ unsigned long long pk(float lo, float hi) {
    return (unsigned long long)__float_as_uint(lo) |
           ((unsigned long long)__float_as_uint(hi) << 32);
}

// Packed fp32x2 FMA (Blackwell): d = a*b + c per 32-bit lane
__device__ __forceinline__ unsigned long long fma2(unsigned long long a,
                                                   unsigned long long b,
                                                   unsigned long long c) {
    unsigned long long d;
    asm("fma.rn.f32x2 %0, %1, %2, %3;" : "=l"(d) : "l"(a), "l"(b), "l"(c));
    return d;
}

// Sign-aware monotonic float<->uint mapping (so atomicMin on uint == min on float,
// including negative values from catastrophic cancellation)
__device__ __forceinline__ unsigned fmap(float f) {
    unsigned u = __float_as_uint(f);
    return (u & 0x80000000u) ? ~u : (u ^ 0x80000000u);
}
__device__ __forceinline__ float finv(unsigned k) {
    unsigned u = (k & 0x80000000u) ? (k ^ 0x80000000u) : ~k;
    return __uint_as_float(u);
}

// ---------------------------------------------------------------------------
// Kernel 1: transform outputs -> query points q (and |q|^2), init min slots
// retrajs[b,n,i] = s_b * sum_j outputs[b,n,j] * c2w[b,i,j]  +  c2w[b,i,3]
// ---------------------------------------------------------------------------
__global__ void qprep_kernel(const float* __restrict__ outputs,
                             const float* __restrict__ c2ws,
                             const float* __restrict__ scales,
                             int N, int Qtot) {
    int idx = blockIdx.x * blockDim.x + threadIdx.x;
    if (idx >= MAXQ) return;
    if (idx < Qtot) {
        int b = idx / N, n = idx % N;
        float s = scales[b];
        const float* o = outputs + ((size_t)b * N + n) * 3;
        const float* c = c2ws + (size_t)b * 16;
        float ox = o[0], oy = o[1], oz = o[2];
        float qx = fmaf(s, fmaf(ox, c[0], fmaf(oy, c[1], oz * c[2])),  c[3]);
        float qy = fmaf(s, fmaf(ox, c[4], fmaf(oy, c[5], oz * c[6])),  c[7]);
        float qz = fmaf(s, fmaf(ox, c[8], fmaf(oy, c[9], oz * c[10])), c[11]);
        g_q[idx] = make_float4(qx, qy, qz, qx * qx + qy * qy + qz * qz);
    } else {
        g_q[idx] = make_float4(0.f, 0.f, 0.f, 0.f);
    }
    g_dmin[idx] = 0xFFFFFFFFu;
}

// ---------------------------------------------------------------------------
// Kernel 2: pack means into duplicated f32x2 lanes: (-2x,-2x,-2y,-2y),(-2z,-2z,m2,m2)
// ---------------------------------------------------------------------------
__global__ void mprep_kernel(const float* __restrict__ means, int M) {
    int m = blockIdx.x * blockDim.x + threadIdx.x;
    if (m >= M) return;
    float x = means[3 * m + 0];
    float y = means[3 * m + 1];
    float z = means[3 * m + 2];
    float w = fmaf(x, x, fmaf(y, y, z * z));
    g_means2[2 * m + 0] = make_ulonglong2(pk(-2.f * x, -2.f * x), pk(-2.f * y, -2.f * y));
    g_means2[2 * m + 1] = make_ulonglong2(pk(-2.f * z, -2.f * z), pk(w, w));
}

// ---------------------------------------------------------------------------
// Kernel 3 (hot): per-q min over this block's chunk of means.
// Each thread owns 16 consecutive q's as 8 f32x2 triples. For each mean:
//   t = m2 - 2 q.m  (3 packed FMAs, shared packed mean operands from smem)
// ---------------------------------------------------------------------------
__global__ void __launch_bounds__(256, 2) nn_min_kernel(int M) {
    __shared__ ulonglong2 sm[2 * TILE];   // 16 KB

    const int tid  = threadIdx.x;
    const int base = tid * 16;

    unsigned long long QX[8], QY[8], QZ[8];
#pragma unroll
    for (int p = 0; p < 8; ++p) {
        float4 a = g_q[base + 2 * p];
        float4 b = g_q[base + 2 * p + 1];
        QX[p] = pk(a.x, b.x);
        QY[p] = pk(a.y, b.y);
        QZ[p] = pk(a.z, b.z);
    }

    float best[16];
#pragma unroll
    for (int k = 0; k < 16; ++k) best[k] = __int_as_float(0x7f800000);  // +inf

    const int chunk = (M + gridDim.x - 1) / gridDim.x;
    const int start = blockIdx.x * chunk;
    const int end   = min(start + chunk, M);

    for (int t0 = start; t0 < end; t0 += TILE) {
        const int cnt = min(TILE, end - t0);
        __syncthreads();
        for (int i = tid; i < cnt * 2; i += 256)
            sm[i] = g_means2[(size_t)t0 * 2 + i];
        __syncthreads();

        for (int j = 0; j < cnt; ++j) {
            const ulonglong2 e0 = sm[2 * j];       // (A=-2x dup, B=-2y dup)
            const ulonglong2 e1 = sm[2 * j + 1];   // (C=-2z dup, W=m2  dup)
#pragma unroll
            for (int p = 0; p < 8; ++p) {
                unsigned long long acc = fma2(QZ[p], e1.x, e1.y);
                acc = fma2(QY[p], e0.y, acc);
                acc = fma2(QX[p], e0.x, acc);
                float lo = __uint_as_float((unsigned)acc);
                float hi = __uint_as_float((unsigned)(acc >> 32));
                best[2 * p]     = fminf(best[2 * p],     lo);
                best[2 * p + 1] = fminf(best[2 * p + 1], hi);
            }
        }
    }

#pragma unroll
    for (int k = 0; k < 16; ++k)
        atomicMin(&g_dmin[base + k], fmap(best[k]));
}

// ---------------------------------------------------------------------------
// Kernel 4: unmap, add |q|^2, clamp, hinge, mean -> out[0]
// ---------------------------------------------------------------------------
__global__ void reduce_kernel(float* __restrict__ out, int Qtot) {
    __shared__ float wsum[32];
    const int tid = threadIdx.x;

    float s = 0.f;
    for (int idx = tid; idx < Qtot; idx += blockDim.x) {
        float t  = finv(g_dmin[idx]);
        float d2 = t + g_q[idx].w;
        float d  = fmaxf(d2, 0.f);
        s += fmaxf(MARGIN - d, 0.f);
    }
#pragma unroll
    for (int o = 16; o; o >>= 1) s += __shfl_down_sync(0xFFFFFFFFu, s, o);
    if ((tid & 31) == 0) wsum[tid >> 5] = s;
    __syncthreads();
    if (tid < 32) {
        float v = (tid < (int)(blockDim.x >> 5)) ? wsum[tid] : 0.f;
#pragma unroll
        for (int o = 16; o; o >>= 1) v += __shfl_down_sync(0xFFFFFFFFu, v, o);
        if (tid == 0) out[0] = v / (float)Qtot;
    }
}

extern "C" void kernel_launch(void* const* d_in, const int* in_sizes, int n_in,
                              void* d_out, int out_size) {
    const float* outputs = (const float*)d_in[0];  // (B, N, 3)
    const float* c2ws    = (const float*)d_in[1];  // (B, 4, 4)
    const float* scales  = (const float*)d_in[2];  // (B,)
    const float* means   = (const float*)d_in[3];  // (M, 3)

    int B = in_sizes[2];
    int Q = in_sizes[0] / 3;         // B*N
    int N = (B > 0) ? (Q / B) : 0;
    int M = in_sizes[3] / 3;
    if (Q > MAXQ) Q = MAXQ;
    if (M > MAXM) M = MAXM;

    qprep_kernel<<<(MAXQ + 255) / 256, 256>>>(outputs, c2ws, scales, N, Q);
    mprep_kernel<<<(M + 255) / 256, 256>>>(means, M);
    nn_min_kernel<<<304, 256>>>(M);
    reduce_kernel<<<1, 512>>>((float*)d_out, Q);
}

// round 9
// speedup vs baseline: 2.6631x; 2.6631x over previous
#include <cuda_runtime.h>
#include <math_constants.h>

#define MAXQ   4096
#define MAXM   100000
#define MARGIN 0.0625f

// Grid over [-6,6]^3, cell 0.25 => any mean within dist 0.25 of a query lies
// in the 27-cell neighborhood of the query's (clamped) cell. Exact for any data.
#define GS     48
#define NC     (GS * GS * GS)      // 110592 = 108 * 1024
#define SCANBLK 108                // NC / 1024

// ---- static device scratch (no runtime allocation) ----
__device__ float4 g_q[MAXQ];         // query x,y,z (w unused)
__device__ int    g_cnt[NC];         // per-cell mean count
__device__ int    g_off[NC];         // exclusive offsets
__device__ int    g_fill[NC];        // scatter cursors
__device__ float4 g_pts[MAXM];       // means sorted by cell
__device__ int    g_bsum[SCANBLK];   // scan block sums
__device__ int    g_bscan[SCANBLK];  // scanned block sums
__device__ float  g_partial[1024];   // per-block loss partials

__device__ __forceinline__ int cell1d(float v) {
    int c = (int)floorf((v + 6.0f) * 4.0f);
    return min(max(c, 0), GS - 1);
}

// ---------------------------------------------------------------------------
// Kernel 1: zero counts + transform outputs -> query points
// ---------------------------------------------------------------------------
__global__ void prep_kernel(const float* __restrict__ outputs,
                            const float* __restrict__ c2ws,
                            const float* __restrict__ scales,
                            int N, int Qtot) {
    int i = blockIdx.x * blockDim.x + threadIdx.x;
    if (i < NC) g_cnt[i] = 0;
    if (i < Qtot) {
        int b = i / N, n = i % N;
        float s = scales[b];
        const float* o = outputs + ((size_t)b * N + n) * 3;
        const float* c = c2ws + (size_t)b * 16;
        float ox = o[0], oy = o[1], oz = o[2];
        float qx = fmaf(s, fmaf(ox, c[0], fmaf(oy, c[1], oz * c[2])),  c[3]);
        float qy = fmaf(s, fmaf(ox, c[4], fmaf(oy, c[5], oz * c[6])),  c[7]);
        float qz = fmaf(s, fmaf(ox, c[8], fmaf(oy, c[9], oz * c[10])), c[11]);
        g_q[i] = make_float4(qx, qy, qz, 0.f);
    }
}

// ---------------------------------------------------------------------------
// Kernel 2: count means per cell
// ---------------------------------------------------------------------------
__global__ void count_kernel(const float* __restrict__ means, int M) {
    int m = blockIdx.x * blockDim.x + threadIdx.x;
    if (m >= M) return;
    int cx = cell1d(means[3 * m + 0]);
    int cy = cell1d(means[3 * m + 1]);
    int cz = cell1d(means[3 * m + 2]);
    atomicAdd(&g_cnt[(cz * GS + cy) * GS + cx], 1);
}

// ---------------------------------------------------------------------------
// Kernels 3-5: exclusive scan of g_cnt -> g_off (3-stage hierarchical)
// ---------------------------------------------------------------------------
__global__ void scanA_kernel() {
    __shared__ int ss[256];
    const int tid  = threadIdx.x;
    const int base = blockIdx.x * 1024 + tid * 4;
    int4 v = *(const int4*)&g_cnt[base];
    int s = v.x + v.y + v.z + v.w;
    ss[tid] = s;
    __syncthreads();
#pragma unroll
    for (int off = 1; off < 256; off <<= 1) {
        int t = (tid >= off) ? ss[tid - off] : 0;
        __syncthreads();
        ss[tid] += t;
        __syncthreads();
    }
    int excl = ss[tid] - s;
    g_off[base + 0] = excl;
    g_off[base + 1] = excl + v.x;
    g_off[base + 2] = excl + v.x + v.y;
    g_off[base + 3] = excl + v.x + v.y + v.z;
    if (tid == 255) g_bsum[blockIdx.x] = ss[255];
}

__global__ void scanB_kernel() {
    __shared__ int ss[128];
    const int tid = threadIdx.x;
    int s = (tid < SCANBLK) ? g_bsum[tid] : 0;
    ss[tid] = s;
    __syncthreads();
#pragma unroll
    for (int off = 1; off < 128; off <<= 1) {
        int t = (tid >= off) ? ss[tid - off] : 0;
        __syncthreads();
        ss[tid] += t;
        __syncthreads();
    }
    if (tid < SCANBLK) g_bscan[tid] = ss[tid] - s;
}

__global__ void scanC_kernel() {
    const int add  = g_bscan[blockIdx.x];
    const int base = blockIdx.x * 1024 + threadIdx.x * 4;
#pragma unroll
    for (int k = 0; k < 4; ++k) {
        int o = g_off[base + k] + add;
        g_off[base + k]  = o;
        g_fill[base + k] = o;
    }
}

// ---------------------------------------------------------------------------
// Kernel 6: scatter means into cell-sorted order
// ---------------------------------------------------------------------------
__global__ void scatter_kernel(const float* __restrict__ means, int M) {
    int m = blockIdx.x * blockDim.x + threadIdx.x;
    if (m >= M) return;
    float x = means[3 * m + 0];
    float y = means[3 * m + 1];
    float z = means[3 * m + 2];
    int c = (cell1d(z) * GS + cell1d(y)) * GS + cell1d(x);
    int pos = atomicAdd(&g_fill[c], 1);
    g_pts[pos] = make_float4(x, y, z, 0.f);
}

// ---------------------------------------------------------------------------
// Kernel 7: warp-per-query nearest-neighbor over 27-cell neighborhood.
// x-adjacent cells are contiguous after the sort -> 9 contiguous ranges.
// ---------------------------------------------------------------------------
__global__ void __launch_bounds__(256) query_kernel(int Q) {
    __shared__ float wterm[8];
    const int tid  = threadIdx.x;
    const int lane = tid & 31;
    const int warp = tid >> 5;
    const int qid  = blockIdx.x * 8 + warp;

    float best = CUDART_INF_F;
    if (qid < Q) {
        float4 qv = g_q[qid];
        int cx = cell1d(qv.x), cy = cell1d(qv.y), cz = cell1d(qv.z);
        int x0 = max(cx - 1, 0), x1 = min(cx + 1, GS - 1);
        int y0 = max(cy - 1, 0), y1 = min(cy + 1, GS - 1);
        int z0 = max(cz - 1, 0), z1 = min(cz + 1, GS - 1);
        for (int zi = z0; zi <= z1; ++zi) {
            for (int yi = y0; yi <= y1; ++yi) {
                int cA = (zi * GS + yi) * GS + x0;
                int cB = (zi * GS + yi) * GS + x1;
                int s0 = g_off[cA];
                int e  = g_off[cB] + g_cnt[cB];
                for (int t = s0 + lane; t < e; t += 32) {
                    float4 m = g_pts[t];
                    float dx = qv.x - m.x;
                    float dy = qv.y - m.y;
                    float dz = qv.z - m.z;
                    float d2 = fmaf(dx, dx, fmaf(dy, dy, dz * dz));
                    best = fminf(best, d2);
                }
            }
        }
    }
#pragma unroll
    for (int o = 16; o; o >>= 1)
        best = fminf(best, __shfl_xor_sync(0xFFFFFFFFu, best, o));
    if (lane == 0) {
        float term = (qid < Q) ? fmaxf(MARGIN - fmaxf(best, 0.f), 0.f) : 0.f;
        wterm[warp] = term;
    }
    __syncthreads();
    if (tid == 0) {
        float s = 0.f;
#pragma unroll
        for (int w = 0; w < 8; ++w) s += wterm[w];
        g_partial[blockIdx.x] = s;
    }
}

// ---------------------------------------------------------------------------
// Kernel 8: finalize (sum partials, divide by Q)
// ---------------------------------------------------------------------------
__global__ void finalize_kernel(float* __restrict__ out, int nb, int Q) {
    __shared__ float ws[32];
    const int tid = threadIdx.x;
    float s = 0.f;
    for (int i = tid; i < nb; i += blockDim.x) s += g_partial[i];
#pragma unroll
    for (int o = 16; o; o >>= 1) s += __shfl_down_sync(0xFFFFFFFFu, s, o);
    if ((tid & 31) == 0) ws[tid >> 5] = s;
    __syncthreads();
    if (tid < 32) {
        float v = (tid < (int)(blockDim.x >> 5)) ? ws[tid] : 0.f;
#pragma unroll
        for (int o = 16; o; o >>= 1) v += __shfl_down_sync(0xFFFFFFFFu, v, o);
        if (tid == 0) out[0] = v / (float)Q;
    }
}

extern "C" void kernel_launch(void* const* d_in, const int* in_sizes, int n_in,
                              void* d_out, int out_size) {
    const float* outputs = (const float*)d_in[0];  // (B, N, 3)
    const float* c2ws    = (const float*)d_in[1];  // (B, 4, 4)
    const float* scales  = (const float*)d_in[2];  // (B,)
    const float* means   = (const float*)d_in[3];  // (M, 3)

    int B = in_sizes[2];
    int Q = in_sizes[0] / 3;              // B*N
    int N = (B > 0) ? (Q / B) : 0;
    int M = in_sizes[3] / 3;
    if (Q > MAXQ) Q = MAXQ;
    if (M > MAXM) M = MAXM;

    int nqb = (Q + 7) / 8;                // 8 warps (queries) per block

    prep_kernel   <<<(NC + 255) / 256, 256>>>(outputs, c2ws, scales, N, Q);
    count_kernel  <<<(M + 255) / 256, 256>>>(means, M);
    scanA_kernel  <<<SCANBLK, 256>>>();
    scanB_kernel  <<<1, 128>>>();
    scanC_kernel  <<<SCANBLK, 256>>>();
    scatter_kernel<<<(M + 255) / 256, 256>>>(means, M);
    query_kernel  <<<nqb, 256>>>(Q);
    finalize_kernel<<<1, 512>>>((float*)d_out, nqb, Q);
}

// round 10
// speedup vs baseline: 2.8409x; 1.0667x over previous
#include <cuda_runtime.h>
#include <math_constants.h>

#define MAXQ    4096
#define MAXM    100000
#define MARGIN  0.0625f

// Grid over [-5,5]^3, cell 0.25. Clamped binning is 1-Lipschitz, so any mean
// within distance 0.25 of a query lies in the query cell's 27-neighborhood.
// Exact for arbitrary inputs.
#define GS      40
#define NC      (GS * GS * GS)          // 64000
#define SCANBLK 63
#define NCPAD   (SCANBLK * 1024)        // 64512 (padded cells always zero)

#define FP_SCALE 17179869184.0          // 2^34

// ---- static device scratch (zero-initialized at load; invariants restored each run) ----
__device__ float4             g_q[MAXQ];
__device__ int                g_cnt[NCPAD];        // zeroed again by scan_kernel
__device__ int                g_off[NCPAD + 1];
__device__ int                g_fill[NCPAD];
__device__ float4             g_pts[MAXM];
__device__ unsigned long long g_state[SCANBLK];    // lookback: flag<<62 | value
__device__ unsigned long long g_acc;               // fixed-point loss accumulator
__device__ unsigned int       g_done;              // ticket counter

__device__ __forceinline__ int cell1d(float v) {
    int c = (int)floorf((v + 5.0f) * 4.0f);
    return min(max(c, 0), GS - 1);
}

// ---------------------------------------------------------------------------
// Kernel 1: reset lookback state + transform queries + count means per cell.
// (g_cnt is zero on entry: static init on first call, scan_kernel restores it.)
// ---------------------------------------------------------------------------
__global__ void prep_count_kernel(const float* __restrict__ outputs,
                                  const float* __restrict__ c2ws,
                                  const float* __restrict__ scales,
                                  const float* __restrict__ means,
                                  int N, int Qtot, int M) {
    int gid = blockIdx.x * blockDim.x + threadIdx.x;

    if (gid < SCANBLK) g_state[gid] = 0ull;

    if (gid < Qtot) {
        int b = gid / N, n = gid % N;
        float s = scales[b];
        const float* o = outputs + ((size_t)b * N + n) * 3;
        const float* c = c2ws + (size_t)b * 16;
        float ox = o[0], oy = o[1], oz = o[2];
        float qx = fmaf(s, fmaf(ox, c[0], fmaf(oy, c[1], oz * c[2])),  c[3]);
        float qy = fmaf(s, fmaf(ox, c[4], fmaf(oy, c[5], oz * c[6])),  c[7]);
        float qz = fmaf(s, fmaf(ox, c[8], fmaf(oy, c[9], oz * c[10])), c[11]);
        g_q[gid] = make_float4(qx, qy, qz, 0.f);
    }

    if (gid < M) {
        int cx = cell1d(means[3 * gid + 0]);
        int cy = cell1d(means[3 * gid + 1]);
        int cz = cell1d(means[3 * gid + 2]);
        atomicAdd(&g_cnt[(cz * GS + cy) * GS + cx], 1);
    }
}

// ---------------------------------------------------------------------------
// Kernel 2: single-kernel ordered exclusive scan (decoupled lookback).
// Writes g_off and g_fill; zeroes g_cnt behind itself (restores invariant).
// 63 blocks x 256 threads, 4 cells/thread. All blocks co-resident -> no deadlock.
// ---------------------------------------------------------------------------
__global__ void __launch_bounds__(256) scan_kernel() {
    __shared__ int ws_incl[8];
    __shared__ int ws_excl[8];
    __shared__ int sh_prefix;

    const int tid  = threadIdx.x;
    const int bid  = blockIdx.x;
    const int lane = tid & 31;
    const int w    = tid >> 5;
    const int base = bid * 1024 + tid * 4;

    int4 v = *(const int4*)&g_cnt[base];
    int s = v.x + v.y + v.z + v.w;

    // warp inclusive scan of s
    int inc = s;
#pragma unroll
    for (int o = 1; o < 32; o <<= 1) {
        int t = __shfl_up_sync(0xFFFFFFFFu, inc, o);
        if (lane >= o) inc += t;
    }
    if (lane == 31) ws_incl[w] = inc;
    __syncthreads();
    if (tid < 8) {
        int x = ws_incl[tid];
        int e = 0;
#pragma unroll
        for (int k = 0; k < 8; ++k) {     // tiny serial scan, 8 elems
            int t = ws_incl[k];
            if (k < tid) e += t;
        }
        ws_excl[tid] = e;
    }
    __syncthreads();

    const int block_total = ws_excl[7] + ws_incl[7];
    const int excl = (inc - s) + ws_excl[w];

    // decoupled lookback (thread 0)
    if (tid == 0) {
        atomicExch(&g_state[bid], (1ull << 62) | (unsigned long long)block_total);
        unsigned long long prefix = 0;
        for (int i = bid - 1; i >= 0;) {
            unsigned long long st;
            do { st = atomicAdd(&g_state[i], 0ull); } while ((st >> 62) == 0ull);
            prefix += st & 0x3FFFFFFFFFFFFFFFull;
            if ((st >> 62) == 2ull) break;
            --i;
        }
        atomicExch(&g_state[bid],
                   (2ull << 62) | (unsigned long long)(prefix + block_total));
        sh_prefix = (int)prefix;
    }
    __syncthreads();

    const int p = sh_prefix + excl;
    g_off[base + 0]  = p;
    g_off[base + 1]  = p + v.x;
    g_off[base + 2]  = p + v.x + v.y;
    g_off[base + 3]  = p + v.x + v.y + v.z;
    g_fill[base + 0] = p;
    g_fill[base + 1] = p + v.x;
    g_fill[base + 2] = p + v.x + v.y;
    g_fill[base + 3] = p + v.x + v.y + v.z;
    *(int4*)&g_cnt[base] = make_int4(0, 0, 0, 0);   // restore zero-invariant

    if (bid == SCANBLK - 1 && tid == 255)
        g_off[NCPAD] = p + v.x + v.y + v.z + v.w;
}

// ---------------------------------------------------------------------------
// Kernel 3: scatter means into cell-sorted order
// ---------------------------------------------------------------------------
__global__ void scatter_kernel(const float* __restrict__ means, int M) {
    int m = blockIdx.x * blockDim.x + threadIdx.x;
    if (m >= M) return;
    float x = means[3 * m + 0];
    float y = means[3 * m + 1];
    float z = means[3 * m + 2];
    int c = (cell1d(z) * GS + cell1d(y)) * GS + cell1d(x);
    int pos = atomicAdd(&g_fill[c], 1);
    g_pts[pos] = make_float4(x, y, z, 0.f);
}

// ---------------------------------------------------------------------------
// Kernel 4: warp-per-query NN over 9 contiguous segments (x-adjacent cells are
// contiguous after the sort), fused deterministic reduction:
// fixed-point u64 atomicAdd + ticket; last block writes out & resets scratch.
// ---------------------------------------------------------------------------
__global__ void __launch_bounds__(256) query_kernel(float* __restrict__ out, int Q) {
    __shared__ float wterm[8];
    const int tid  = threadIdx.x;
    const int lane = tid & 31;
    const int warp = tid >> 5;
    const int qid  = blockIdx.x * 8 + warp;

    float best = CUDART_INF_F;
    if (qid < Q) {
        float4 qv = g_q[qid];
        int cx = cell1d(qv.x), cy = cell1d(qv.y), cz = cell1d(qv.z);
        int x0 = max(cx - 1, 0), x1 = min(cx + 1, GS - 1);
        int y0 = max(cy - 1, 0), y1 = min(cy + 1, GS - 1);
        int z0 = max(cz - 1, 0), z1 = min(cz + 1, GS - 1);
        for (int zi = z0; zi <= z1; ++zi) {
            for (int yi = y0; yi <= y1; ++yi) {
                int row = (zi * GS + yi) * GS;
                int s0  = g_off[row + x0];
                int e   = g_off[row + x1 + 1];
                for (int t = s0 + lane; t < e; t += 32) {
                    float4 m = g_pts[t];
                    float dx = qv.x - m.x;
                    float dy = qv.y - m.y;
                    float dz = qv.z - m.z;
                    float d2 = fmaf(dx, dx, fmaf(dy, dy, dz * dz));
                    best = fminf(best, d2);
                }
            }
        }
    }
#pragma unroll
    for (int o = 16; o; o >>= 1)
        best = fminf(best, __shfl_xor_sync(0xFFFFFFFFu, best, o));
    if (lane == 0)
        wterm[warp] = (qid < Q) ? fmaxf(MARGIN - fmaxf(best, 0.f), 0.f) : 0.f;
    __syncthreads();

    if (tid == 0) {
        double s = 0.0;
#pragma unroll
        for (int w = 0; w < 8; ++w) s += (double)wterm[w];
        unsigned long long fx = (unsigned long long)__double2ll_rn(s * FP_SCALE);
        atomicAdd(&g_acc, fx);
        __threadfence();
        if (atomicAdd(&g_done, 1u) == gridDim.x - 1) {
            unsigned long long tot = atomicExch(&g_acc, 0ull);   // read + reset
            atomicExch(&g_done, 0u);                             // reset ticket
            out[0] = (float)(((double)tot / FP_SCALE) / (double)Q);
        }
    }
}

extern "C" void kernel_launch(void* const* d_in, const int* in_sizes, int n_in,
                              void* d_out, int out_size) {
    const float* outputs = (const float*)d_in[0];  // (B, N, 3)
    const float* c2ws    = (const float*)d_in[1];  // (B, 4, 4)
    const float* scales  = (const float*)d_in[2];  // (B,)
    const float* means   = (const float*)d_in[3];  // (M, 3)

    int B = in_sizes[2];
    int Q = in_sizes[0] / 3;              // B*N
    int N = (B > 0) ? (Q / B) : 0;
    int M = in_sizes[3] / 3;
    if (Q > MAXQ) Q = MAXQ;
    if (M > MAXM) M = MAXM;

    int work = M > Q ? M : Q;
    int nb1  = (work + 255) / 256;        // covers M, Q, and SCANBLK resets
    int nqb  = (Q + 7) / 8;

    prep_count_kernel<<<nb1, 256>>>(outputs, c2ws, scales, means, N, Q, M);
    scan_kernel      <<<SCANBLK, 256>>>();
    scatter_kernel   <<<(M + 255) / 256, 256>>>(means, M);
    query_kernel     <<<nqb, 256>>>((float*)d_out, Q);
}